// round 8
// baseline (speedup 1.0000x reference)
#include <cuda_runtime.h>

// ---------------------------------------------------------------------------
// Permutohedral-lattice bilateral filter, d=4 (z,y,x,intensity), dp1=5.
// Direct-mapped lattice table (no hashing): every lattice key has all 4
// coords == r (mod 5); key = 5*b + r with b in a small box (interval-proven).
// Split value layout: float4 (q0..q3) + float (w) per vertex position.
// Zeroing protocol: occupied A-rows are re-zeroed inside k_slice (A is not
// read by slice); the occupancy table is cleared inside k_compact (after its
// single read). Static zero-init covers launch #1. Unoccupied rows are never
// written, so blur's neighbor reads of them return 0 (= "missing vertex").
// g_count is zeroed inside k_splat (before compact uses it).
// ---------------------------------------------------------------------------

#define DIMX 96
#define NPIX (96*96*96)          // 884736
#define NBLK ((NPIX + 255) / 256)

// b-field boxes (include +-4 probe slack and >=1 pad on each face)
#define R_SZ0 36
#define R_SZ1 36
#define R_SZ2 28
#define R_SZ3 26
#define OFF0 6
#define OFF1 17
#define OFF2 18
#define OFF3 19
#define S_B3 1
#define S_B2 (R_SZ3)              // 26
#define S_B1 (R_SZ2*R_SZ3)        // 728
#define S_B0 (R_SZ1*R_SZ2*R_SZ3)  // 26208
#define S_R  (R_SZ0*S_B0)         // 943488
#define TBL  (5*S_R)              // 4717440 (divisible by 16)
#define SUM_SB (S_B0+S_B1+S_B2+S_B3)  // 26963

#define SC0 2.886751345948129f   // sqrt(2/3)*5/sqrt(2)
#define SC1 1.6666666666666667f  // sqrt(2/3)*5/sqrt(6)
#define SC2 1.1785113019775793f  // sqrt(2/3)*5/sqrt(12)
#define SC3 0.9128709291752769f  // sqrt(2/3)*5/sqrt(20)
#define EPS64 2.220446049250313e-16f

#define BBLK (148*8)             // fully-resident single wave @ 256 thr

__device__ unsigned char g_tblb[TBL];     // occupancy marks (cleared in compact)
__device__ unsigned g_plist[TBL];         // compact list: pos | (r<<24)
__device__ float4   g_v4A[TBL];
__device__ float4   g_v4B[TBL];
__device__ float    g_v1A[TBL];
__device__ float    g_v1B[TBL];
__device__ uint2    g_pixrec[NPIX * 5];   // (.x = table pos, .y = bary bits)
__device__ int      g_count;

__device__ __forceinline__ void red_add_v4(float4* addr, float a, float b, float c, float d) {
    asm volatile("red.global.add.v4.f32 [%0], {%1, %2, %3, %4};"
                 :: "l"(addr), "f"(a), "f"(b), "f"(c), "f"(d) : "memory");
}
__device__ __forceinline__ void red_add_f(float* addr, float a) {
    asm volatile("red.global.add.f32 [%0], %1;" :: "l"(addr), "f"(a) : "memory");
}

// Exact fp32 replication of the reference elevation/rank/bary math.
__device__ __forceinline__ void compute_lattice(int n, const float* __restrict__ image,
                                                int pos[5], float bary[5]) {
    int x = n % DIMX;
    int t = n / DIMX;
    int y = t % DIMX;
    int z = t / DIMX;

    float cf0 = ((float)z / 5.0f) * SC0;
    float cf1 = ((float)y / 5.0f) * SC1;
    float cf2 = ((float)x / 5.0f) * SC2;
    float cf3 = (image[n] * 4.0f) * SC3;   // image / 0.25

    float e[5];
    float sm = 0.0f;
    e[4] = sm - 4.0f * cf3; sm += cf3;
    e[3] = sm - 3.0f * cf2; sm += cf2;
    e[2] = sm - 2.0f * cf1; sm += cf1;
    e[1] = sm - 1.0f * cf0; sm += cf0;
    e[0] = sm;

    float rem0[5], diff[5];
    int sum_rd = 0;
    #pragma unroll
    for (int i = 0; i < 5; i++) {
        float rd = rintf(e[i] / 5.0f);      // round-half-even, matches jnp.round
        rem0[i] = rd * 5.0f;
        diff[i] = e[i] - rem0[i];
        sum_rd += (int)rd;
    }

    int rank[5];
    #pragma unroll
    for (int i = 0; i < 5; i++) {
        int c = 0;
        #pragma unroll
        for (int j = 0; j < 5; j++)
            c += (diff[j] > diff[i]) || ((diff[j] == diff[i]) && (j < i));
        c += sum_rd;
        if (c < 0)      { c += 5; rem0[i] += 5.0f; }
        else if (c > 4) { c -= 5; rem0[i] -= 5.0f; }
        rank[i] = c;
    }

    float b[6] = {0.f, 0.f, 0.f, 0.f, 0.f, 0.f};
    #pragma unroll
    for (int i = 0; i < 5; i++) {
        float v = (e[i] - rem0[i]) / 5.0f;
        b[4 - rank[i]] += v;
        b[5 - rank[i]] -= v;
    }
    b[0] += 1.0f + b[5];
    #pragma unroll
    for (int r = 0; r < 5; r++) bary[r] = b[r];

    int cc0 = (int)rem0[0], cc1 = (int)rem0[1], cc2 = (int)rem0[2], cc3 = (int)rem0[3];
    #pragma unroll
    for (int r = 0; r < 5; r++) {
        int k0 = cc0 + ((rank[0] < 5 - r) ? r : r - 5);
        int k1 = cc1 + ((rank[1] < 5 - r) ? r : r - 5);
        int k2 = cc2 + ((rank[2] < 5 - r) ? r : r - 5);
        int k3 = cc3 + ((rank[3] < 5 - r) ? r : r - 5);
        // All k_i == r (mod 5); exact integer division.
        int b0 = (k0 - r) / 5 + OFF0;
        int b1 = (k1 - r) / 5 + OFF1;
        int b2 = (k2 - r) / 5 + OFF2;
        int b3 = (k3 - r) / 5 + OFF3;
        pos[r] = r * S_R + b0 * S_B0 + b1 * S_B1 + b2 * S_B2 + b3;
    }
}

// --- K1: fused build + splat (also zeroes g_count for compact) ---------------
__global__ void k_splat(const float* __restrict__ image, const float* __restrict__ input) {
    int n = blockIdx.x * blockDim.x + threadIdx.x;
    if (n == 0) g_count = 0;
    if (n >= NPIX) return;
    int pos[5];
    float bary[5];
    compute_lattice(n, image, pos, bary);
    float q0 = input[0 * NPIX + n];
    float q1 = input[1 * NPIX + n];
    float q2 = input[2 * NPIX + n];
    float q3 = input[3 * NPIX + n];
    #pragma unroll
    for (int r = 0; r < 5; r++) {
        int p = pos[r];
        float w = bary[r];
        g_tblb[p] = 1;
        g_pixrec[r * NPIX + n] = make_uint2((unsigned)p, __float_as_uint(w));
        red_add_v4(&g_v4A[p], w * q0, w * q1, w * q2, w * q3);
        red_add_f(&g_v1A[p], w);
    }
}

// --- K2: compact (4 flags/thread, warp-ordered) + clear table in-place -------
__global__ void k_compact() {
    int i = blockIdx.x * blockDim.x + threadIdx.x;   // uint index
    if (i >= TBL / 4) return;
    unsigned* tbl32 = reinterpret_cast<unsigned*>(g_tblb);
    unsigned v = tbl32[i];
    int cnt = (v & 1u) + ((v >> 8) & 1u) + ((v >> 16) & 1u) + ((v >> 24) & 1u);
    int lane = threadIdx.x & 31;
    int pre = cnt;
    #pragma unroll
    for (int o = 1; o < 32; o <<= 1) {
        int t = __shfl_up_sync(0xFFFFFFFFu, pre, o);
        if (lane >= o) pre += t;
    }
    int tot = __shfl_sync(0xFFFFFFFFu, pre, 31);
    int excl = pre - cnt;
    int base = 0;
    if (lane == 31 && tot > 0) base = atomicAdd(&g_count, tot);
    base = __shfl_sync(0xFFFFFFFFu, base, 31);
    if (cnt > 0) {
        tbl32[i] = 0u;            // restore zero invariant for next launch
        int idx = base + excl;
        int pos0 = i * 4;
        #pragma unroll
        for (int k = 0; k < 4; k++) {
            if ((v >> (8 * k)) & 1u) {
                int pos = pos0 + k;
                unsigned r = (unsigned)pos / (unsigned)S_R;
                g_plist[idx++] = (unsigned)pos | (r << 24);
            }
        }
    }
}

// --- K3..7: blur sweep, 2 entries per iteration for MLP ----------------------
__device__ __forceinline__ void blur_one(unsigned p,
                                         const float4* __restrict__ s4,
                                         const float* __restrict__ s1,
                                         float4* __restrict__ d4,
                                         float* __restrict__ d1,
                                         int dpn, int dpw, int dmn, int dmw) {
    int pos = (int)(p & 0xFFFFFFu);
    unsigned r = p >> 24;
    int n1 = pos + ((r == 4u) ? dpw : dpn);
    int n2 = pos + ((r == 0u) ? dmw : dmn);

    float4 a = s4[pos];
    float4 b = s4[n1];
    float4 c = s4[n2];
    float  a4 = s1[pos];
    float  b4 = s1[n1];
    float  c4 = s1[n2];

    float4 o;
    o.x = 0.5f * a.x + 0.25f * (b.x + c.x);
    o.y = 0.5f * a.y + 0.25f * (b.y + c.y);
    o.z = 0.5f * a.z + 0.25f * (b.z + c.z);
    o.w = 0.5f * a.w + 0.25f * (b.w + c.w);
    float o4 = 0.5f * a4 + 0.25f * (b4 + c4);
    d4[pos] = o;
    d1[pos] = o4;
}

__global__ void k_blur(const float4* __restrict__ s4, const float* __restrict__ s1,
                       float4* __restrict__ d4, float* __restrict__ d1,
                       int dpn, int dpw, int dmn, int dmw) {
    int total = g_count;
    int stride = gridDim.x * blockDim.x;
    int e = blockIdx.x * blockDim.x + threadIdx.x;
    for (; e + stride < total; e += 2 * stride) {
        unsigned pa = g_plist[e];
        unsigned pb = g_plist[e + stride];
        blur_one(pa, s4, s1, d4, d1, dpn, dpw, dmn, dmw);
        blur_one(pb, s4, s1, d4, d1, dpn, dpw, dmn, dmw);
    }
    if (e < total) {
        blur_one(g_plist[e], s4, s1, d4, d1, dpn, dpw, dmn, dmw);
    }
}

// --- K8: slice + normalize; then reset occupied A-rows (A unused by slice) ---
__global__ void k_slice(const float4* __restrict__ v4, const float* __restrict__ v1,
                        float* __restrict__ out) {
    int stride = gridDim.x * blockDim.x;
    for (int n = blockIdx.x * blockDim.x + threadIdx.x; n < NPIX; n += stride) {
        float a0 = 0.f, a1 = 0.f, a2 = 0.f, a3 = 0.f, a4 = 0.f;
        #pragma unroll
        for (int r = 0; r < 5; r++) {
            uint2 rec = g_pixrec[r * NPIX + n];
            float w = __uint_as_float(rec.y);
            float4 v = v4[rec.x];
            float  vv = v1[rec.x];
            a0 += w * v.x;
            a1 += w * v.y;
            a2 += w * v.z;
            a3 += w * v.w;
            a4 += w * vv;
        }
        float den = a4 + EPS64;
        out[0 * NPIX + n] = a0 / den;
        out[1 * NPIX + n] = a1 / den;
        out[2 * NPIX + n] = a2 / den;
        out[3 * NPIX + n] = a3 / den;
    }
    // Restore the zero invariant on the A-side for the next launch/replay.
    int total = g_count;
    for (int e = blockIdx.x * blockDim.x + threadIdx.x; e < total; e += stride) {
        int pos = (int)(g_plist[e] & 0xFFFFFFu);
        g_v4A[pos] = make_float4(0.f, 0.f, 0.f, 0.f);
        g_v1A[pos] = 0.f;
    }
}

// ---------------------------------------------------------------------------

extern "C" void kernel_launch(void* const* d_in, const int* in_sizes, int n_in,
                              void* d_out, int out_size) {
    const float* input = (const float*)d_in[0];
    const float* image = (const float*)d_in[1];
    if (n_in >= 2 && in_sizes[0] == NPIX) {
        image = (const float*)d_in[0];
        input = (const float*)d_in[1];
    }
    float* out = (float*)d_out;

    const int TB = 256;

    float4 *v4A, *v4B; float *v1A, *v1B;
    cudaGetSymbolAddress((void**)&v4A, g_v4A);
    cudaGetSymbolAddress((void**)&v4B, g_v4B);
    cudaGetSymbolAddress((void**)&v1A, g_v1A);
    cudaGetSymbolAddress((void**)&v1B, g_v1B);

    k_splat<<<NBLK, TB>>>(image, input);
    k_compact<<<(TBL / 4 + TB - 1) / TB, TB>>>();

    // Per-direction position deltas. sj[j] = stride of the b-field that gets
    // the -4 coordinate step (0 for j=4: all coords +1).
    const int sj[5] = {S_B0, S_B1, S_B2, S_B3, 0};
    float4* s4 = v4A; float* s1 = v1A;
    float4* d4 = v4B; float* d1 = v1B;
    for (int j = 0; j < 5; j++) {
        int dpn = S_R - sj[j];                     // +dir, r<4
        int dpw = -4 * S_R + SUM_SB - sj[j];       // +dir, r==4
        int dmn = -S_R + sj[j];                    // -dir, r>0
        int dmw = 4 * S_R - SUM_SB + sj[j];        // -dir, r==0
        k_blur<<<BBLK, TB>>>(s4, s1, d4, d1, dpn, dpw, dmn, dmw);
        float4* t4 = s4; s4 = d4; d4 = t4;
        float*  t1 = s1; s1 = d1; d1 = t1;
    }
    // After 5 passes the result is in the B-side; slice reads it and also
    // resets the A-side rows + nothing else touches A afterwards.
    k_slice<<<BBLK, TB>>>(s4, s1, out);
}

// round 9
// speedup vs baseline: 1.0610x; 1.0610x over previous
#include <cuda_runtime.h>

// ---------------------------------------------------------------------------
// Permutohedral-lattice bilateral filter, d=4 (z,y,x,intensity), dp1=5.
// Direct-mapped lattice table (no hashing): every lattice key has all 4
// coords == r (mod 5); key = 5*b + r with b in a small box (interval-proven).
// Split value layout: float4 (q0..q3) + float (w) per vertex position.
// Zeroing protocol: occupied A-rows are re-zeroed inside k_slice (A is not
// read by slice); the occupancy table is cleared inside k_compact (after its
// single read). Static zero-init covers launch #1. Unoccupied rows are never
// written, so blur's neighbor reads of them return 0 (= "missing vertex").
// g_count is zeroed inside k_splat (before compact uses it).
// ---------------------------------------------------------------------------

#define DIMX 96
#define NPIX (96*96*96)          // 884736
#define NBLK ((NPIX + 255) / 256)

// b-field boxes (include +-4 probe slack and >=1 pad on each face)
#define R_SZ0 36
#define R_SZ1 36
#define R_SZ2 28
#define R_SZ3 26
#define OFF0 6
#define OFF1 17
#define OFF2 18
#define OFF3 19
#define S_B3 1
#define S_B2 (R_SZ3)              // 26
#define S_B1 (R_SZ2*R_SZ3)        // 728
#define S_B0 (R_SZ1*R_SZ2*R_SZ3)  // 26208
#define S_R  (R_SZ0*S_B0)         // 943488
#define TBL  (5*S_R)              // 4717440 (divisible by 64)
#define SUM_SB (S_B0+S_B1+S_B2+S_B3)  // 26963

#define SC0 2.886751345948129f   // sqrt(2/3)*5/sqrt(2)
#define SC1 1.6666666666666667f  // sqrt(2/3)*5/sqrt(6)
#define SC2 1.1785113019775793f  // sqrt(2/3)*5/sqrt(12)
#define SC3 0.9128709291752769f  // sqrt(2/3)*5/sqrt(20)
#define EPS64 2.220446049250313e-16f

#define BBLK (148*8)             // fully-resident single wave @ 256 thr

__device__ unsigned char g_tblb[TBL];     // occupancy marks (cleared in compact)
__device__ unsigned g_plist[TBL];         // compact list: pos | (r<<24)
__device__ float4   g_v4A[TBL];
__device__ float4   g_v4B[TBL];
__device__ float    g_v1A[TBL];
__device__ float    g_v1B[TBL];
__device__ uint2    g_pixrec[NPIX * 5];   // (.x = table pos, .y = bary bits)
__device__ int      g_count;

__device__ __forceinline__ void red_add_v4(float4* addr, float a, float b, float c, float d) {
    asm volatile("red.global.add.v4.f32 [%0], {%1, %2, %3, %4};"
                 :: "l"(addr), "f"(a), "f"(b), "f"(c), "f"(d) : "memory");
}
__device__ __forceinline__ void red_add_f(float* addr, float a) {
    asm volatile("red.global.add.f32 [%0], %1;" :: "l"(addr), "f"(a) : "memory");
}

// Exact fp32 replication of the reference elevation/rank/bary math.
__device__ __forceinline__ void compute_lattice(int n, const float* __restrict__ image,
                                                int pos[5], float bary[5]) {
    int x = n % DIMX;
    int t = n / DIMX;
    int y = t % DIMX;
    int z = t / DIMX;

    float cf0 = ((float)z / 5.0f) * SC0;
    float cf1 = ((float)y / 5.0f) * SC1;
    float cf2 = ((float)x / 5.0f) * SC2;
    float cf3 = (image[n] * 4.0f) * SC3;   // image / 0.25

    float e[5];
    float sm = 0.0f;
    e[4] = sm - 4.0f * cf3; sm += cf3;
    e[3] = sm - 3.0f * cf2; sm += cf2;
    e[2] = sm - 2.0f * cf1; sm += cf1;
    e[1] = sm - 1.0f * cf0; sm += cf0;
    e[0] = sm;

    float rem0[5], diff[5];
    int sum_rd = 0;
    #pragma unroll
    for (int i = 0; i < 5; i++) {
        float rd = rintf(e[i] / 5.0f);      // round-half-even, matches jnp.round
        rem0[i] = rd * 5.0f;
        diff[i] = e[i] - rem0[i];
        sum_rd += (int)rd;
    }

    int rank[5];
    #pragma unroll
    for (int i = 0; i < 5; i++) {
        int c = 0;
        #pragma unroll
        for (int j = 0; j < 5; j++)
            c += (diff[j] > diff[i]) || ((diff[j] == diff[i]) && (j < i));
        c += sum_rd;
        if (c < 0)      { c += 5; rem0[i] += 5.0f; }
        else if (c > 4) { c -= 5; rem0[i] -= 5.0f; }
        rank[i] = c;
    }

    float b[6] = {0.f, 0.f, 0.f, 0.f, 0.f, 0.f};
    #pragma unroll
    for (int i = 0; i < 5; i++) {
        float v = (e[i] - rem0[i]) / 5.0f;
        b[4 - rank[i]] += v;
        b[5 - rank[i]] -= v;
    }
    b[0] += 1.0f + b[5];
    #pragma unroll
    for (int r = 0; r < 5; r++) bary[r] = b[r];

    int cc0 = (int)rem0[0], cc1 = (int)rem0[1], cc2 = (int)rem0[2], cc3 = (int)rem0[3];
    #pragma unroll
    for (int r = 0; r < 5; r++) {
        int k0 = cc0 + ((rank[0] < 5 - r) ? r : r - 5);
        int k1 = cc1 + ((rank[1] < 5 - r) ? r : r - 5);
        int k2 = cc2 + ((rank[2] < 5 - r) ? r : r - 5);
        int k3 = cc3 + ((rank[3] < 5 - r) ? r : r - 5);
        // All k_i == r (mod 5); exact integer division.
        int b0 = (k0 - r) / 5 + OFF0;
        int b1 = (k1 - r) / 5 + OFF1;
        int b2 = (k2 - r) / 5 + OFF2;
        int b3 = (k3 - r) / 5 + OFF3;
        pos[r] = r * S_R + b0 * S_B0 + b1 * S_B1 + b2 * S_B2 + b3;
    }
}

// --- K1: fused build + splat with warp-pair atomic aggregation ---------------
// NPIX % blockDim == 0, so every warp is full: unguarded full-mask shuffles.
__global__ void k_splat(const float* __restrict__ image, const float* __restrict__ input) {
    int n = blockIdx.x * blockDim.x + threadIdx.x;
    if (n == 0) g_count = 0;
    int pos[5];
    float bary[5];
    compute_lattice(n, image, pos, bary);
    float q0 = input[0 * NPIX + n];
    float q1 = input[1 * NPIX + n];
    float q2 = input[2 * NPIX + n];
    float q3 = input[3 * NPIX + n];
    bool even = ((threadIdx.x & 1) == 0);
    #pragma unroll
    for (int r = 0; r < 5; r++) {
        int p = pos[r];
        float w = bary[r];
        g_tblb[p] = 1;
        g_pixrec[r * NPIX + n] = make_uint2((unsigned)p, __float_as_uint(w));

        float v0 = w * q0, v1 = w * q1, v2 = w * q2, v3 = w * q3, vw = w;
        int   pp = __shfl_xor_sync(0xFFFFFFFFu, p, 1);
        float u0 = __shfl_xor_sync(0xFFFFFFFFu, v0, 1);
        float u1 = __shfl_xor_sync(0xFFFFFFFFu, v1, 1);
        float u2 = __shfl_xor_sync(0xFFFFFFFFu, v2, 1);
        float u3 = __shfl_xor_sync(0xFFFFFFFFu, v3, 1);
        float uw = __shfl_xor_sync(0xFFFFFFFFu, vw, 1);
        bool match = (pp == p);
        if (match) { v0 += u0; v1 += u1; v2 += u2; v3 += u3; vw += uw; }
        if (!match || even) {
            red_add_v4(&g_v4A[p], v0, v1, v2, v3);
            red_add_f(&g_v1A[p], vw);
        }
    }
}

// --- K2: compact (16 flags/thread via uint4, warp-ordered) + clear in-place --
__global__ void k_compact() {
    int i = blockIdx.x * blockDim.x + threadIdx.x;   // uint4 index
    if (i >= TBL / 16) return;
    uint4* tbl128 = reinterpret_cast<uint4*>(g_tblb);
    uint4 v = tbl128[i];
    unsigned any = v.x | v.y | v.z | v.w;
    int cnt = __popc(v.x) + __popc(v.y) + __popc(v.z) + __popc(v.w);  // flags are 0/1 bytes
    int lane = threadIdx.x & 31;
    int pre = cnt;
    #pragma unroll
    for (int o = 1; o < 32; o <<= 1) {
        int t = __shfl_up_sync(0xFFFFFFFFu, pre, o);
        if (lane >= o) pre += t;
    }
    int tot = __shfl_sync(0xFFFFFFFFu, pre, 31);
    int excl = pre - cnt;
    int base = 0;
    if (lane == 31 && tot > 0) base = atomicAdd(&g_count, tot);
    base = __shfl_sync(0xFFFFFFFFu, base, 31);
    if (any) {
        tbl128[i] = make_uint4(0u, 0u, 0u, 0u);   // restore zero invariant
        int idx = base + excl;
        int pos0 = i * 16;
        unsigned words[4] = {v.x, v.y, v.z, v.w};
        #pragma unroll
        for (int wdi = 0; wdi < 4; wdi++) {
            unsigned wv = words[wdi];
            #pragma unroll
            for (int k = 0; k < 4; k++) {
                if ((wv >> (8 * k)) & 1u) {
                    int pos = pos0 + wdi * 4 + k;
                    unsigned r = (unsigned)pos / (unsigned)S_R;
                    g_plist[idx++] = (unsigned)pos | (r << 24);
                }
            }
        }
    }
}

// --- K3..7: blur sweep (simple grid-stride; R7 form) --------------------------
__global__ void k_blur(const float4* __restrict__ s4, const float* __restrict__ s1,
                       float4* __restrict__ d4, float* __restrict__ d1,
                       int dpn, int dpw, int dmn, int dmw) {
    int total = g_count;
    for (int e = blockIdx.x * blockDim.x + threadIdx.x; e < total;
         e += gridDim.x * blockDim.x) {
        unsigned p = g_plist[e];
        int pos = (int)(p & 0xFFFFFFu);
        unsigned r = p >> 24;
        int n1 = pos + ((r == 4u) ? dpw : dpn);
        int n2 = pos + ((r == 0u) ? dmw : dmn);

        float4 a = s4[pos];
        float  a4 = s1[pos];
        float4 b = s4[n1];
        float  b4 = s1[n1];
        float4 c = s4[n2];
        float  c4 = s1[n2];

        float4 o;
        o.x = 0.5f * a.x + 0.25f * (b.x + c.x);
        o.y = 0.5f * a.y + 0.25f * (b.y + c.y);
        o.z = 0.5f * a.z + 0.25f * (b.z + c.z);
        o.w = 0.5f * a.w + 0.25f * (b.w + c.w);
        float o4 = 0.5f * a4 + 0.25f * (b4 + c4);
        d4[pos] = o;
        d1[pos] = o4;
    }
}

// --- K8: slice + normalize; then reset occupied A-rows (A unused by slice) ---
__global__ void k_slice(const float4* __restrict__ v4, const float* __restrict__ v1,
                        float* __restrict__ out) {
    int stride = gridDim.x * blockDim.x;
    for (int n = blockIdx.x * blockDim.x + threadIdx.x; n < NPIX; n += stride) {
        float a0 = 0.f, a1 = 0.f, a2 = 0.f, a3 = 0.f, a4 = 0.f;
        #pragma unroll
        for (int r = 0; r < 5; r++) {
            uint2 rec = g_pixrec[r * NPIX + n];
            float w = __uint_as_float(rec.y);
            float4 v = v4[rec.x];
            float  vv = v1[rec.x];
            a0 += w * v.x;
            a1 += w * v.y;
            a2 += w * v.z;
            a3 += w * v.w;
            a4 += w * vv;
        }
        float den = a4 + EPS64;
        out[0 * NPIX + n] = a0 / den;
        out[1 * NPIX + n] = a1 / den;
        out[2 * NPIX + n] = a2 / den;
        out[3 * NPIX + n] = a3 / den;
    }
    // Restore the zero invariant on the A-side for the next launch/replay.
    int total = g_count;
    for (int e = blockIdx.x * blockDim.x + threadIdx.x; e < total; e += stride) {
        int pos = (int)(g_plist[e] & 0xFFFFFFu);
        g_v4A[pos] = make_float4(0.f, 0.f, 0.f, 0.f);
        g_v1A[pos] = 0.f;
    }
}

// ---------------------------------------------------------------------------

extern "C" void kernel_launch(void* const* d_in, const int* in_sizes, int n_in,
                              void* d_out, int out_size) {
    const float* input = (const float*)d_in[0];
    const float* image = (const float*)d_in[1];
    if (n_in >= 2 && in_sizes[0] == NPIX) {
        image = (const float*)d_in[0];
        input = (const float*)d_in[1];
    }
    float* out = (float*)d_out;

    const int TB = 256;

    float4 *v4A, *v4B; float *v1A, *v1B;
    cudaGetSymbolAddress((void**)&v4A, g_v4A);
    cudaGetSymbolAddress((void**)&v4B, g_v4B);
    cudaGetSymbolAddress((void**)&v1A, g_v1A);
    cudaGetSymbolAddress((void**)&v1B, g_v1B);

    k_splat<<<NBLK, TB>>>(image, input);
    k_compact<<<(TBL / 16 + TB - 1) / TB, TB>>>();

    // Per-direction position deltas. sj[j] = stride of the b-field that gets
    // the -4 coordinate step (0 for j=4: all coords +1).
    const int sj[5] = {S_B0, S_B1, S_B2, S_B3, 0};
    float4* s4 = v4A; float* s1 = v1A;
    float4* d4 = v4B; float* d1 = v1B;
    for (int j = 0; j < 5; j++) {
        int dpn = S_R - sj[j];                     // +dir, r<4
        int dpw = -4 * S_R + SUM_SB - sj[j];       // +dir, r==4
        int dmn = -S_R + sj[j];                    // -dir, r>0
        int dmw = 4 * S_R - SUM_SB + sj[j];        // -dir, r==0
        k_blur<<<BBLK, TB>>>(s4, s1, d4, d1, dpn, dpw, dmn, dmw);
        float4* t4 = s4; s4 = d4; d4 = t4;
        float*  t1 = s1; s1 = d1; d1 = t1;
    }
    // After 5 passes the result is in the B-side; slice reads it and also
    // resets the A-side rows.
    k_slice<<<BBLK, TB>>>(s4, s1, out);
}